// round 4
// baseline (speedup 1.0000x reference)
#include <cuda_runtime.h>
#include <cstdint>

#define B_   32
#define T_   2048
#define XD   64
#define ZD   128
#define H_   512
#define TAU  16

// ---------------- scratch (device globals; no allocations allowed) ----------
__device__ float g_Vx[16][64][64];      // [k][d][i]
__device__ float g_Vz[16][128][64];     // [k][e][i]
__device__ float g_VzSS[16][128][64];   // suffix sums over k ; [0] = full sum
__device__ float g_C[16][64];
__device__ float g_CSS[16][64];
__device__ float g_dummy;

// ---------------- packed f32x2 helpers --------------------------------------
typedef unsigned long long u64;
union F2U { u64 u; float2 f; };

__device__ __forceinline__ u64 pack2(float x) {
    u64 d;
    asm("mov.b64 %0, {%1, %1};" : "=l"(d) : "f"(x));
    return d;
}
__device__ __forceinline__ u64 ffma2(u64 a, u64 b, u64 c) {
    u64 d;
    asm("fma.rn.f32x2 %0, %1, %2, %3;" : "=l"(d) : "l"(a), "l"(b), "l"(c));
    return d;
}

// =============================================================================
// Kernel 0: dummy (rotates which launch ncu captures -> fused gets profiled)
// =============================================================================
__global__ void dummy_kernel() { g_dummy = 1.0f; }

// =============================================================================
// Kernel 1: v = W1@W2 (over h), c = b1@W2 + b2. Reads W1 once (400MB). No copy.
// =============================================================================
__global__ __launch_bounds__(256) void vc_kernel(
    const float* __restrict__ W1, const float* __restrict__ b1,
    const float* __restrict__ W2, const float* __restrict__ b2)
{
    __shared__ float s_w2[512];
    int blk = blockIdx.x;              // = i*16 + k
    int i = blk >> 4, k = blk & 15;
    const float* src = W1 + (size_t)blk * (192 * 512);
    const float* w2p = W2 + (size_t)blk * 512;

    for (int j = threadIdx.x; j < 512; j += 256) s_w2[j] = w2p[j];
    __syncthreads();

    int warp = threadIdx.x >> 5, lane = threadIdx.x & 31;

    float w2r[4][4];
    #pragma unroll
    for (int j = 0; j < 4; j++) {
        int q = lane + 32 * j;
        #pragma unroll
        for (int c = 0; c < 4; c++) w2r[j][c] = s_w2[q * 4 + c];
    }

    for (int d = warp; d < 192; d += 8) {
        const float4* s4 = (const float4*)(src + (size_t)d * 512);
        float acc = 0.f;
        #pragma unroll
        for (int j = 0; j < 4; j++) {
            int q = lane + 32 * j;
            float4 v = s4[q];
            acc += v.x * w2r[j][0] + v.y * w2r[j][1]
                 + v.z * w2r[j][2] + v.w * w2r[j][3];
        }
        #pragma unroll
        for (int o = 16; o; o >>= 1) acc += __shfl_xor_sync(0xffffffffu, acc, o);
        if (lane == 0) {
            if (d < 64) g_Vx[k][d][i] = acc;
            else        g_Vz[k][d - 64][i] = acc;
        }
    }

    if (warp == 0) {
        const float* b1p = b1 + (size_t)blk * 512;
        float acc = 0.f;
        for (int j = lane; j < 512; j += 32) acc += b1p[j] * s_w2[j];
        #pragma unroll
        for (int o = 16; o; o >>= 1) acc += __shfl_xor_sync(0xffffffffu, acc, o);
        if (lane == 0) g_C[k][i] = acc + b2[blk];
    }
}

// =============================================================================
// Kernel 2: suffix sums over k for vz and c (tiny)
// =============================================================================
__global__ __launch_bounds__(256) void prefix_kernel()
{
    int idx = blockIdx.x * 256 + threadIdx.x;
    if (idx < 128 * 64) {
        int e = idx >> 6, i = idx & 63;
        float run = 0.f;
        #pragma unroll
        for (int k = 15; k >= 0; k--) {
            run += g_Vz[k][e][i];
            g_VzSS[k][e][i] = run;
        }
    } else if (idx < 128 * 64 + 64) {
        int i = idx - 128 * 64;
        float run = 0.f;
        #pragma unroll
        for (int k = 15; k >= 0; k--) {
            run += g_C[k][i];
            g_CSS[k][i] = run;
        }
    }
}

// =============================================================================
// Kernel 3 (fused): 1536 blocks.
//   bid % 3 == 0  -> GEMM block m = bid/3 (512 blocks)  [FMA-pipe bound]
//   else          -> transpose-copy block (1024 blocks) [HBM bound]
// The two populations use disjoint resources and overlap on the SMs.
// =============================================================================
#define TT 128
#define XR 66
#define ZR 66

__device__ __forceinline__ void compute_chunk(
    const float* __restrict__ abase, int astr,
    const float* __restrict__ wbase, int ibase, u64 (&acc)[4][4])
{
    const float* a0p = abase;
    const float* a1p = abase + astr;
    const float* a2p = abase + 2 * astr;
    const float* a3p = abase + 3 * astr;
    const float* wp  = wbase + ibase;
    #pragma unroll 2
    for (int kd = 0; kd < 64; kd++) {
        ulonglong2 wA = *(const ulonglong2*)(wp + kd * 64);
        ulonglong2 wB = *(const ulonglong2*)(wp + kd * 64 + 4);
        u64 a0 = pack2(a0p[kd]);
        u64 a1 = pack2(a1p[kd]);
        u64 a2 = pack2(a2p[kd]);
        u64 a3 = pack2(a3p[kd]);
        acc[0][0] = ffma2(a0, wA.x, acc[0][0]); acc[0][1] = ffma2(a0, wA.y, acc[0][1]);
        acc[0][2] = ffma2(a0, wB.x, acc[0][2]); acc[0][3] = ffma2(a0, wB.y, acc[0][3]);
        acc[1][0] = ffma2(a1, wA.x, acc[1][0]); acc[1][1] = ffma2(a1, wA.y, acc[1][1]);
        acc[1][2] = ffma2(a1, wB.x, acc[1][2]); acc[1][3] = ffma2(a1, wB.y, acc[1][3]);
        acc[2][0] = ffma2(a2, wA.x, acc[2][0]); acc[2][1] = ffma2(a2, wA.y, acc[2][1]);
        acc[2][2] = ffma2(a2, wB.x, acc[2][2]); acc[2][3] = ffma2(a2, wB.y, acc[2][3]);
        acc[3][0] = ffma2(a3, wA.x, acc[3][0]); acc[3][1] = ffma2(a3, wA.y, acc[3][1]);
        acc[3][2] = ffma2(a3, wB.x, acc[3][2]); acc[3][3] = ffma2(a3, wB.y, acc[3][3]);
    }
}

__device__ __forceinline__ void load_wchunk(const float* __restrict__ gsrc,
                                            float* __restrict__ sdst, int tid)
{
    const float4* s = (const float4*)gsrc;
    float4*       d = (float4*)sdst;
    #pragma unroll
    for (int r = 0; r < 4; r++) d[tid + 256 * r] = s[tid + 256 * r];
}

__global__ __launch_bounds__(256, 2) void fused_kernel(
    const float* __restrict__ z, const float* __restrict__ x,
    const float* __restrict__ W1,
    float* __restrict__ out, float* __restrict__ infl)
{
    int bid = blockIdx.x;
    int tid = threadIdx.x;

    if (bid % 3 != 0) {
        // ---------------- copy path: W1[i][k] -> infl[k][i], 768KB/block ----
        int cb = bid - (bid / 3) - 1;          // 0..1023
        int i = cb >> 4, k = cb & 15;
        const float4* s = (const float4*)(W1 + (size_t)cb * (192 * 512));
        float4*       d = (float4*)(infl + ((size_t)(k * 64 + i)) * (192 * 512));
        #pragma unroll 4
        for (int j = tid; j < 24576; j += 256) d[j] = s[j];
        return;
    }

    // -------------------- GEMM path --------------------
    extern __shared__ float sm[];
    float* s_x = sm;                       // [144][XR]
    float* s_z = s_x + 144 * XR;           // [128][ZR]
    float* s_w = s_z + 128 * ZR;           // [2][64*64]
    float* s_c = s_w + 2 * 4096;           // [64]

    int m  = bid / 3;                      // 0..511
    int b  = m >> 4;
    int t0 = (m & 15) * TT;
    int ig = tid & 7;
    int tg = tid >> 3;
    int tbase = tg * 4;
    int ibase = ig * 8;

    const float4* x4 = (const float4*)(x + (size_t)b * T_ * XD);
    #pragma unroll
    for (int it = 0; it < 9; it++) {
        int idx = tid + 256 * it;          // < 2304
        int col = idx >> 4, dq = idx & 15;
        int gt = t0 - TAU + col;
        float4 v = make_float4(0.f, 0.f, 0.f, 0.f);
        if (gt >= 0) v = x4[(size_t)gt * 16 + dq];
        float* p = s_x + col * XR + dq * 4;
        *(float2*)p       = make_float2(v.x, v.y);
        *(float2*)(p + 2) = make_float2(v.z, v.w);
    }
    const float4* z4 = (const float4*)(z + (size_t)b * T_ * ZD);
    #pragma unroll
    for (int it = 0; it < 8; it++) {
        int idx = tid + 256 * it;          // < 2048
        int tl = idx >> 4, eq = idx & 15;
        float4 v = z4[(size_t)(t0 + tl) * 32 + eq];
        float* p = s_z + tl * ZR + eq * 4;
        *(float2*)p       = make_float2(v.x, v.y);
        *(float2*)(p + 2) = make_float2(v.z, v.w);
    }
    load_wchunk(&g_VzSS[0][0][0], s_w, tid);
    if (tid < 64) s_c[tid] = g_CSS[0][tid];
    __syncthreads();

    u64 acc[4][4];
    #pragma unroll
    for (int r = 0; r < 4; r++)
        #pragma unroll
        for (int c = 0; c < 4; c++) acc[r][c] = 0ull;

    // z half 0, prefetch half-1 weights
    load_wchunk(&g_VzSS[0][64][0], s_w + 4096, tid);
    compute_chunk(s_z + tbase * ZR, ZR, s_w, ibase, acc);
    __syncthreads();

    // reload z half 1, prefetch Vx[0]
    #pragma unroll
    for (int it = 0; it < 8; it++) {
        int idx = tid + 256 * it;
        int tl = idx >> 4, eq = idx & 15;
        float4 v = z4[(size_t)(t0 + tl) * 32 + 16 + eq];
        float* p = s_z + tl * ZR + eq * 4;
        *(float2*)p       = make_float2(v.x, v.y);
        *(float2*)(p + 2) = make_float2(v.z, v.w);
    }
    load_wchunk(&g_Vx[0][0][0], s_w, tid);
    __syncthreads();

    compute_chunk(s_z + tbase * ZR, ZR, s_w + 4096, ibase, acc);
    __syncthreads();

    for (int kk = 0; kk < 16; kk++) {
        if (kk < 15)
            load_wchunk(&g_Vx[kk + 1][0][0], s_w + ((kk + 1) & 1) * 4096, tid);
        compute_chunk(s_x + (tbase + 15 - kk) * XR, XR,
                      s_w + (kk & 1) * 4096, ibase, acc);
        __syncthreads();
    }

    float c0 = s_c[ibase + 0], c1 = s_c[ibase + 1], c2 = s_c[ibase + 2], c3 = s_c[ibase + 3];
    float c4 = s_c[ibase + 4], c5 = s_c[ibase + 5], c6 = s_c[ibase + 6], c7 = s_c[ibase + 7];
    #pragma unroll
    for (int r = 0; r < 4; r++) {
        int t = t0 + tbase + r;
        F2U u0; u0.u = acc[r][0];
        F2U u1; u1.u = acc[r][1];
        F2U u2; u2.u = acc[r][2];
        F2U u3; u3.u = acc[r][3];
        float4* op = (float4*)(out + ((size_t)b * T_ + t) * XD + ibase);
        op[0] = make_float4(u0.f.x + c0, u0.f.y + c1, u1.f.x + c2, u1.f.y + c3);
        op[1] = make_float4(u2.f.x + c4, u2.f.y + c5, u3.f.x + c6, u3.f.y + c7);
    }
}

// =============================================================================
// Kernel 4: fixup for t < 16 (subtract invalid-k sz + c via suffix sums)
// =============================================================================
__global__ __launch_bounds__(128) void fixup_kernel(
    const float* __restrict__ z, float* __restrict__ out)
{
    int t = blockIdx.x;      // 0..15
    int b = blockIdx.y;      // 0..31
    __shared__ float s_zrow[128];
    __shared__ float s_part[64];

    int tid = threadIdx.x;
    s_zrow[tid] = z[((size_t)b * T_ + t) * ZD + tid];
    __syncthreads();

    int i    = tid & 63;
    int half = tid >> 6;
    const float* w = &g_VzSS[t][half * 64][i];
    float acc = 0.f;
    #pragma unroll
    for (int e0 = 0; e0 < 64; e0++)
        acc += s_zrow[half * 64 + e0] * w[e0 * 64];

    if (half == 1) s_part[i] = acc;
    __syncthreads();
    if (half == 0) {
        float corr = acc + s_part[i] + g_CSS[t][i];
        out[((size_t)b * T_ + t) * XD + i] -= corr;
    }
}

// =============================================================================
extern "C" void kernel_launch(void* const* d_in, const int* in_sizes, int n_in,
                              void* d_out, int out_size)
{
    const float* z  = (const float*)d_in[0];
    const float* x  = (const float*)d_in[1];
    const float* W1 = (const float*)d_in[2];
    const float* b1 = (const float*)d_in[3];
    const float* W2 = (const float*)d_in[4];
    const float* b2 = (const float*)d_in[5];
    float* out  = (float*)d_out;
    float* infl = out + (size_t)B_ * T_ * XD;

    dummy_kernel<<<1, 1>>>();
    vc_kernel<<<1024, 256>>>(W1, b1, W2, b2);
    prefix_kernel<<<33, 256>>>();

    int smem = (144 * XR + 128 * ZR + 2 * 4096 + 64) * (int)sizeof(float);
    cudaFuncSetAttribute(fused_kernel, cudaFuncAttributeMaxDynamicSharedMemorySize, smem);
    fused_kernel<<<1536, 256, smem>>>(z, x, W1, out, infl);

    fixup_kernel<<<dim3(16, 32), 128>>>(z, out);
}

// round 5
// speedup vs baseline: 1.5098x; 1.5098x over previous
#include <cuda_runtime.h>
#include <cstdint>

#define B_   32
#define T_   2048
#define XD   64
#define ZD   128
#define H_   512
#define TAU  16

// ---------------- scratch (device globals; no allocations allowed) ----------
__device__ float g_Vx[16][64][64];      // [k][d][i]
__device__ float g_Vz[16][128][64];     // [k][e][i]
__device__ float g_VzSS[16][128][64];   // suffix sums over k ; [0] = full sum
__device__ float g_C[16][64];
__device__ float g_CSS[16][64];
__device__ float g_dummy;

// ---------------- packed f32x2 helpers --------------------------------------
typedef unsigned long long u64;
union F2U { u64 u; float2 f; };

__device__ __forceinline__ u64 pack2(float x) {
    u64 d;
    asm("mov.b64 %0, {%1, %1};" : "=l"(d) : "f"(x));
    return d;
}
__device__ __forceinline__ u64 ffma2(u64 a, u64 b, u64 c) {
    u64 d;
    asm("fma.rn.f32x2 %0, %1, %2, %3;" : "=l"(d) : "l"(a), "l"(b), "l"(c));
    return d;
}

// =============================================================================
// Kernel 0: dummy — rotates ncu capture slot so the 4th launch (main) profiles
// =============================================================================
__global__ void dummy_kernel() { g_dummy = 1.0f; }

// =============================================================================
// Kernel 1: fused W1 transpose (-> influence output) + v = W1@W2 + c = b1@W2+b2
// =============================================================================
__global__ __launch_bounds__(256) void prep_kernel(
    const float* __restrict__ W1, const float* __restrict__ b1,
    const float* __restrict__ W2, const float* __restrict__ b2,
    float* __restrict__ infl)
{
    __shared__ float s_w2[512];
    int blk = blockIdx.x;              // = i*16 + k
    int i = blk >> 4, k = blk & 15;
    const float* src = W1 + (size_t)blk * (192 * 512);
    float*       dst = infl + ((size_t)(k * 64 + i)) * (192 * 512);
    const float* w2p = W2 + (size_t)blk * 512;

    for (int j = threadIdx.x; j < 512; j += 256) s_w2[j] = w2p[j];
    __syncthreads();

    int warp = threadIdx.x >> 5, lane = threadIdx.x & 31;

    float w2r[4][4];
    #pragma unroll
    for (int j = 0; j < 4; j++) {
        int q = lane + 32 * j;
        #pragma unroll
        for (int c = 0; c < 4; c++) w2r[j][c] = s_w2[q * 4 + c];
    }

    for (int d = warp; d < 192; d += 8) {
        const float4* s4 = (const float4*)(src + (size_t)d * 512);
        float4*       d4 = (float4*)(dst + (size_t)d * 512);
        float acc = 0.f;
        #pragma unroll
        for (int j = 0; j < 4; j++) {
            int q = lane + 32 * j;
            float4 v = s4[q];
            d4[q] = v;                                    // transpose copy
            acc += v.x * w2r[j][0] + v.y * w2r[j][1]
                 + v.z * w2r[j][2] + v.w * w2r[j][3];
        }
        #pragma unroll
        for (int o = 16; o; o >>= 1) acc += __shfl_xor_sync(0xffffffffu, acc, o);
        if (lane == 0) {
            if (d < 64) g_Vx[k][d][i] = acc;
            else        g_Vz[k][d - 64][i] = acc;
        }
    }

    if (warp == 0) {
        const float* b1p = b1 + (size_t)blk * 512;
        float acc = 0.f;
        for (int j = lane; j < 512; j += 32) acc += b1p[j] * s_w2[j];
        #pragma unroll
        for (int o = 16; o; o >>= 1) acc += __shfl_xor_sync(0xffffffffu, acc, o);
        if (lane == 0) g_C[k][i] = acc + b2[blk];
    }
}

// =============================================================================
// Kernel 2: suffix sums over k for vz and c (tiny)
// =============================================================================
__global__ __launch_bounds__(256) void prefix_kernel()
{
    int idx = blockIdx.x * 256 + threadIdx.x;
    if (idx < 128 * 64) {
        int e = idx >> 6, i = idx & 63;
        float run = 0.f;
        #pragma unroll
        for (int k = 15; k >= 0; k--) {
            run += g_Vz[k][e][i];
            g_VzSS[k][e][i] = run;
        }
    } else if (idx < 128 * 64 + 64) {
        int i = idx - 128 * 64;
        float run = 0.f;
        #pragma unroll
        for (int k = 15; k >= 0; k--) {
            run += g_C[k][i];
            g_CSS[k][i] = run;
        }
    }
}

// =============================================================================
// Kernel 3: main fused GEMM v2.
// Tile 128 t x 64 i per block; per thread 8 t x 4 i (16 i-groups per warp ->
// conflict-free 256B-contiguous weight LDS.128; a-loads are float4 broadcast).
// =============================================================================
#define TT 128
#define XR 64
#define ZR 64

__device__ __forceinline__ void compute_chunk(
    const float* __restrict__ abase,           // 8 rows, stride XR
    const float* __restrict__ wbase, int ibase, u64 (&acc)[8][2])
{
    const float4* a4 = (const float4*)abase;   // row r at a4 + r*16
    const float* wp  = wbase + ibase;
    #pragma unroll 2
    for (int kd4 = 0; kd4 < 16; kd4++) {
        float4 av[8];
        #pragma unroll
        for (int r = 0; r < 8; r++) av[r] = a4[r * 16 + kd4];
        #pragma unroll
        for (int j = 0; j < 4; j++) {
            ulonglong2 w = *(const ulonglong2*)(wp + (kd4 * 4 + j) * 64);
            #pragma unroll
            for (int r = 0; r < 8; r++) {
                float a_s = (j == 0) ? av[r].x : (j == 1) ? av[r].y
                          : (j == 2) ? av[r].z : av[r].w;
                u64 a = pack2(a_s);
                acc[r][0] = ffma2(a, w.x, acc[r][0]);
                acc[r][1] = ffma2(a, w.y, acc[r][1]);
            }
        }
    }
}

__device__ __forceinline__ void load_wchunk(const float* __restrict__ gsrc,
                                            float* __restrict__ sdst, int tid)
{
    const float4* s = (const float4*)gsrc;
    float4*       d = (float4*)sdst;
    #pragma unroll
    for (int r = 0; r < 4; r++) d[tid + 256 * r] = s[tid + 256 * r];
}

__global__ __launch_bounds__(256, 2) void main_kernel(
    const float* __restrict__ z, const float* __restrict__ x,
    float* __restrict__ out)
{
    extern __shared__ float sm[];
    float* s_x = sm;                       // [144][64]
    float* s_z = s_x + 144 * XR;           // [128][64]  (one half of z dims)
    float* s_w = s_z + 128 * ZR;           // [2][64*64]
    float* s_c = s_w + 2 * 4096;           // [64]

    int b  = blockIdx.y;
    int t0 = blockIdx.x * TT;
    int tid = threadIdx.x;
    int ig = tid & 15;                     // 16 i-groups x 4 i
    int tg = tid >> 4;                     // 16 t-groups x 8 t
    int tbase = tg * 8;
    int ibase = ig * 4;

    // ---- phase 0: x tile (zero-padded), z half 0, w buf0 = VzFull[0:64] ----
    const float4* x4 = (const float4*)(x + (size_t)b * T_ * XD);
    float4* sx4 = (float4*)s_x;
    #pragma unroll
    for (int it = 0; it < 9; it++) {
        int idx = tid + 256 * it;          // < 2304
        int col = idx >> 4, dq = idx & 15;
        int gt = t0 - TAU + col;
        float4 v = make_float4(0.f, 0.f, 0.f, 0.f);
        if (gt >= 0) v = x4[(size_t)gt * 16 + dq];
        sx4[col * 16 + dq] = v;
    }
    const float4* z4 = (const float4*)(z + (size_t)b * T_ * ZD);
    float4* sz4 = (float4*)s_z;
    #pragma unroll
    for (int it = 0; it < 8; it++) {
        int idx = tid + 256 * it;          // < 2048
        int tl = idx >> 4, eq = idx & 15;
        sz4[tl * 16 + eq] = z4[(size_t)(t0 + tl) * 32 + eq];
    }
    load_wchunk(&g_VzSS[0][0][0], s_w, tid);
    if (tid < 64) s_c[tid] = g_CSS[0][tid];
    __syncthreads();

    u64 acc[8][2];
    #pragma unroll
    for (int r = 0; r < 8; r++) { acc[r][0] = 0ull; acc[r][1] = 0ull; }

    // ---- z half 0, prefetch half-1 weights ----
    load_wchunk(&g_VzSS[0][64][0], s_w + 4096, tid);
    compute_chunk(s_z + tbase * ZR, s_w, ibase, acc);
    __syncthreads();

    // ---- reload z half 1, prefetch Vx[0] into buf0 ----
    #pragma unroll
    for (int it = 0; it < 8; it++) {
        int idx = tid + 256 * it;
        int tl = idx >> 4, eq = idx & 15;
        sz4[tl * 16 + eq] = z4[(size_t)(t0 + tl) * 32 + 16 + eq];
    }
    load_wchunk(&g_Vx[0][0][0], s_w, tid);
    __syncthreads();

    // ---- z half 1 ----
    compute_chunk(s_z + tbase * ZR, s_w + 4096, ibase, acc);
    __syncthreads();

    // ---- 16 x-tap chunks, double-buffered weights ----
    for (int kk = 0; kk < 16; kk++) {
        if (kk < 15)
            load_wchunk(&g_Vx[kk + 1][0][0], s_w + ((kk + 1) & 1) * 4096, tid);
        compute_chunk(s_x + (tbase + 15 - kk) * XR,
                      s_w + (kk & 1) * 4096, ibase, acc);
        __syncthreads();
    }

    // ---- epilogue ----
    float c0 = s_c[ibase + 0], c1 = s_c[ibase + 1];
    float c2 = s_c[ibase + 2], c3 = s_c[ibase + 3];
    #pragma unroll
    for (int r = 0; r < 8; r++) {
        int t = t0 + tbase + r;
        F2U u0; u0.u = acc[r][0];
        F2U u1; u1.u = acc[r][1];
        float4* op = (float4*)(out + ((size_t)b * T_ + t) * XD + ibase);
        op[0] = make_float4(u0.f.x + c0, u0.f.y + c1, u1.f.x + c2, u1.f.y + c3);
    }
}

// =============================================================================
// Kernel 4: fixup for t < 16 (subtract invalid-k sz + c via suffix sums)
// =============================================================================
__global__ __launch_bounds__(128) void fixup_kernel(
    const float* __restrict__ z, float* __restrict__ out)
{
    int t = blockIdx.x;      // 0..15
    int b = blockIdx.y;      // 0..31
    __shared__ float s_zrow[128];
    __shared__ float s_part[64];

    int tid = threadIdx.x;
    s_zrow[tid] = z[((size_t)b * T_ + t) * ZD + tid];
    __syncthreads();

    int i    = tid & 63;
    int half = tid >> 6;
    const float* w = &g_VzSS[t][half * 64][i];
    float acc = 0.f;
    #pragma unroll
    for (int e0 = 0; e0 < 64; e0++)
        acc += s_zrow[half * 64 + e0] * w[e0 * 64];

    if (half == 1) s_part[i] = acc;
    __syncthreads();
    if (half == 0) {
        float corr = acc + s_part[i] + g_CSS[t][i];
        out[((size_t)b * T_ + t) * XD + i] -= corr;
    }
}

// =============================================================================
extern "C" void kernel_launch(void* const* d_in, const int* in_sizes, int n_in,
                              void* d_out, int out_size)
{
    const float* z  = (const float*)d_in[0];
    const float* x  = (const float*)d_in[1];
    const float* W1 = (const float*)d_in[2];
    const float* b1 = (const float*)d_in[3];
    const float* W2 = (const float*)d_in[4];
    const float* b2 = (const float*)d_in[5];
    float* out  = (float*)d_out;
    float* infl = out + (size_t)B_ * T_ * XD;

    dummy_kernel<<<1, 1>>>();
    prep_kernel<<<1024, 256>>>(W1, b1, W2, b2, infl);
    prefix_kernel<<<33, 256>>>();

    int smem = (144 * XR + 128 * ZR + 2 * 4096 + 64) * (int)sizeof(float);
    cudaFuncSetAttribute(main_kernel, cudaFuncAttributeMaxDynamicSharedMemorySize, smem);
    main_kernel<<<dim3(16, 32), 256, smem>>>(z, x, out);

    fixup_kernel<<<dim3(16, 32), 128>>>(z, out);
}